// round 13
// baseline (speedup 1.0000x reference)
#include <cuda_runtime.h>
#include <cuda_fp16.h>
#include <math.h>
#include <stdint.h>

#define NN   100000
#define NPAD 100096          // 782 * 128
#define EE   400000
#define GG   2048
#define DIN  128
#define RANK 256

// ---------------- scratch (device globals: no allocations allowed) ----------
__device__ __half g_hf16[NPAD * RANK];   // h (tanh out) fp16; also x fp16 (lda=K)
__device__ __half g_ah [NPAD * RANK];    // Agg(h) fp16 (lda = K)
__device__ __half g_wh [RANK * RANK];    // (scale-folded) W^T fp16  [n][k]
__device__ float g_woff[3 * RANK];       // rank-1 BN offset per layer
__device__ float g_rhop[NN];
__device__ int   g_cnt   [NN];
__device__ int   g_cursor[NN];
__device__ int   g_rowptr[NN + 1];
__device__ float g_dinv  [NN];
__device__ int   g_esrc[EE];
__device__ float g_ew  [EE];
__device__ int   g_gptr[GG + 1];
__device__ float g_sum  [3 * RANK];      // per-layer BN stats
__device__ float g_sumsq[3 * RANK];
__device__ int   g_part[128];

// ---------------- BN param helper -------------------------------------------
__device__ __forceinline__ void bn_params(int layer, int c,
                                          const float* gamma, const float* beta,
                                          float& sc, float& sh) {
    float mu  = g_sum[layer * RANK + c]   * (1.0f / NN);
    float var = g_sumsq[layer * RANK + c] * (1.0f / NN) - mu * mu;
    sc = gamma[c] * rsqrtf(var + 1e-5f);
    sh = beta[c] - mu * sc;
}

// ---------------- graph preprocessing ----------------------------------------
__global__ void k_init() {
    int i = blockIdx.x * blockDim.x + threadIdx.x;
    if (i < NN) { g_cnt[i] = 0; g_cursor[i] = 0; g_rhop[i] = 0.f; }
    if (i < 3 * RANK) { g_sum[i] = 0.f; g_sumsq[i] = 0.f; g_woff[i] = 0.f; }
}

// hist + convW0 + x->fp16, one launch (independent block ranges)
#define HISTB 1563            // ceil(EE/256)
#define CONVW0B (RANK * DIN / 256)   // 128
#define CONVXB (NN * DIN / 4 / 256)  // 12500
__global__ void k_histconv(const int* __restrict__ dst,
                           const float* __restrict__ W0,
                           const float* __restrict__ x) {
    int b = blockIdx.x;
    if (b < HISTB) {
        int e = b * 256 + threadIdx.x;
        if (e < EE) atomicAdd(&g_cnt[dst[e]], 1);
    } else if (b < HISTB + CONVW0B) {
        int i = (b - HISTB) * 256 + threadIdx.x;     // over RANK*DIN
        int n = i / DIN, k = i - n * DIN;
        g_wh[i] = __float2half_rn(W0[(size_t)k * RANK + n]);
    } else {
        int i4 = (b - HISTB - CONVW0B) * 256 + threadIdx.x;
        if (i4 < NN * DIN / 4) {
            float4 v = ((const float4*)x)[i4];
            __half2 a = __floats2half2_rn(v.x, v.y);
            __half2 c = __floats2half2_rn(v.z, v.w);
            *(uint2*)(g_hf16 + (size_t)i4 * 4) = make_uint2(*(uint32_t*)&a, *(uint32_t*)&c);
        }
    }
}

// dinv + scan phase 1 (block sums)
__global__ void k_dinvscan1() {
    __shared__ int sm[256];
    int b = blockIdx.x, t = threadIdx.x;
    if (b == 0 && t == 0) g_rowptr[NN] = EE;
    int base = b * 1024 + t * 4;
    int s = 0;
    #pragma unroll
    for (int j = 0; j < 4; j++) {
        int i = base + j;
        if (i < NN) {
            int c = g_cnt[i];
            s += c;
            g_dinv[i] = rsqrtf((float)(c + 1));
        }
    }
    sm[t] = s; __syncthreads();
    for (int off = 128; off > 0; off >>= 1) {
        if (t < off) sm[t] += sm[t + off];
        __syncthreads();
    }
    if (t == 0) g_part[b] = sm[0];
}

// scan phase 2 (in-block re-scan of partials) + phase 3 + gptr
__global__ void k_scan3gptr(const int* __restrict__ batch) {
    __shared__ int sm[256];
    __shared__ int sp[128];
    int b = blockIdx.x, t = threadIdx.x;

    if (t < 128) sp[t] = (t < 98) ? g_part[t] : 0;
    __syncthreads();
    for (int off = 1; off < 128; off <<= 1) {
        int u = (t >= off && t < 128) ? sp[t - off] : 0;
        __syncthreads();
        if (t < 128) sp[t] += u;
        __syncthreads();
    }
    int blockPrefix = (b > 0) ? sp[b - 1] : 0;   // exclusive

    int base = b * 1024 + t * 4;
    int v[4]; int s = 0;
    #pragma unroll
    for (int j = 0; j < 4; j++) { int i = base + j; v[j] = (i < NN) ? g_cnt[i] : 0; s += v[j]; }
    sm[t] = s; __syncthreads();
    for (int off = 1; off < 256; off <<= 1) {
        int u = (t >= off) ? sm[t - off] : 0;
        __syncthreads();
        sm[t] += u;
        __syncthreads();
    }
    int off0 = blockPrefix + (sm[t] - s);
    int run = 0;
    #pragma unroll
    for (int j = 0; j < 4; j++) {
        int i = base + j;
        if (i < NN) {
            g_rowptr[i] = off0 + run;
            int bi = batch[i];
            if (i == 0) {
                for (int g = 0; g <= bi; g++) g_gptr[g] = 0;
            } else {
                int bp = batch[i - 1];
                for (int g = bp + 1; g <= bi; g++) g_gptr[g] = i;
            }
            if (i == NN - 1) {
                for (int g = bi + 1; g <= GG; g++) g_gptr[g] = NN;
            }
        }
        run += v[j];
    }
}

__global__ void k_scatter(const int* __restrict__ src, const int* __restrict__ dst) {
    int e = blockIdx.x * blockDim.x + threadIdx.x;
    if (e >= EE) return;
    int s = src[e], d = dst[e];
    int pos = g_rowptr[d] + atomicAdd(&g_cursor[d], 1);
    float ds = g_dinv[s];
    g_esrc[pos] = s;
    g_ew[pos]   = ds * g_dinv[d];
    atomicAdd(&g_rhop[d], ds);
}

// ---------------- fused per-layer-boundary kernel ----------------------------
// blocks [0,nagg): aggregation (K cols) h->g_ah
// blocks [nagg, nagg+npool): global max pool of `layer`
// blocks [nagg+npool, +convB): convert W_next (scale-folded by stats[layer])
// blocks [last 32): rank-1 offset for layer+1
#define ANPB 16
__global__ void __launch_bounds__(256)
k_aggpool(int K, int nagg, int npool, int layer,
          const float* __restrict__ gamma, const float* __restrict__ beta,
          float* __restrict__ out, const float* __restrict__ Wnext) {
    __shared__ uint4 psm[256];
    int bid = blockIdx.x;
    int tid = threadIdx.x;

    if (bid < nagg) {
        // ---- aggregation (x2 unroll; mean degree ~4) ----
        int ncg  = K >> 3;
        int cg   = (tid & (ncg - 1)) * 8;
        int sub  = tid / ncg;
        int nsub = 256 / ncg;
        int v0   = bid * ANPB;

        for (int n = sub; n < ANPB; n += nsub) {
            int v = v0 + n;
            if (v >= NN) break;
            int beg = g_rowptr[v], end = g_rowptr[v + 1];
            float di = g_dinv[v];
            float w0 = di * di;

            float acc[8];
            {
                uint4 u = *(const uint4*)(g_hf16 + (size_t)v * K + cg);
                const __half2* hp = (const __half2*)&u;
                #pragma unroll
                for (int j = 0; j < 4; j++) {
                    float2 f = __half22float2(hp[j]);
                    acc[2 * j]     = w0 * f.x;
                    acc[2 * j + 1] = w0 * f.y;
                }
            }
            int e = beg;
            for (; e + 2 <= end; e += 2) {
                float w1 = g_ew[e], w2 = g_ew[e + 1];
                int   s1 = g_esrc[e], s2 = g_esrc[e + 1];
                uint4 u1 = *(const uint4*)(g_hf16 + (size_t)s1 * K + cg);
                uint4 u2 = *(const uint4*)(g_hf16 + (size_t)s2 * K + cg);
                const __half2* h1 = (const __half2*)&u1;
                const __half2* h2 = (const __half2*)&u2;
                #pragma unroll
                for (int j = 0; j < 4; j++) {
                    float2 f1 = __half22float2(h1[j]);
                    float2 f2 = __half22float2(h2[j]);
                    acc[2 * j]     = fmaf(w1, f1.x, acc[2 * j]);
                    acc[2 * j + 1] = fmaf(w1, f1.y, acc[2 * j + 1]);
                    acc[2 * j]     = fmaf(w2, f2.x, acc[2 * j]);
                    acc[2 * j + 1] = fmaf(w2, f2.y, acc[2 * j + 1]);
                }
            }
            for (; e < end; e++) {
                float w = g_ew[e];
                int   s = g_esrc[e];
                uint4 u = *(const uint4*)(g_hf16 + (size_t)s * K + cg);
                const __half2* hp = (const __half2*)&u;
                #pragma unroll
                for (int j = 0; j < 4; j++) {
                    float2 f = __half22float2(hp[j]);
                    acc[2 * j]     = fmaf(w, f.x, acc[2 * j]);
                    acc[2 * j + 1] = fmaf(w, f.y, acc[2 * j + 1]);
                }
            }

            __align__(16) __half o[8];
            #pragma unroll
            for (int j = 0; j < 8; j++) o[j] = __float2half_rn(acc[j]);
            *(uint4*)(g_ah + (size_t)v * K + cg) = *(uint4*)o;
        }
    } else if (bid < nagg + npool) {
        // ---- pool: warp-wide full-row loads, packed half2 max ----
        int g = bid - nagg;
        int beg = g_gptr[g], end = g_gptr[g + 1];
        int cg  = (tid & 31) * 8;     // 8 columns per thread
        int sub = tid >> 5;           // 8 row subsets

        __half2 ninf = __float2half2_rn(-1e30f);
        __half2 mx[4] = { ninf, ninf, ninf, ninf };
        for (int r = beg + sub; r < end; r += 8) {
            uint4 u = *(const uint4*)(g_hf16 + (size_t)r * RANK + cg);
            const __half2* hp = (const __half2*)&u;
            #pragma unroll
            for (int j = 0; j < 4; j++) mx[j] = __hmax2(mx[j], hp[j]);
        }
        psm[tid] = *(uint4*)mx;
        __syncthreads();
        if (tid < 32) {
            __half2 m[4];
            *(uint4*)m = psm[tid];
            #pragma unroll
            for (int s = 1; s < 8; s++) {
                __half2 t2[4];
                *(uint4*)t2 = psm[tid + 32 * s];
                #pragma unroll
                for (int j = 0; j < 4; j++) m[j] = __hmax2(m[j], t2[j]);
            }
            int c0 = tid * 8;
            float vals[8];
            #pragma unroll
            for (int j = 0; j < 4; j++) {
                float2 f = __half22float2(m[j]);
                vals[2 * j] = f.x; vals[2 * j + 1] = f.y;
            }
            #pragma unroll
            for (int j = 0; j < 8; j++) {
                float sc, sh;
                bn_params(layer, c0 + j, gamma, beta, sc, sh);
                vals[j] = (end > beg) ? fmaf(sc, vals[j], sh) : 0.0f;
            }
            *(float4*)(out + (size_t)g * RANK + c0)     = *(float4*)&vals[0];
            *(float4*)(out + (size_t)g * RANK + c0 + 4) = *(float4*)&vals[4];
        }
    } else {
        int convB = RANK * RANK / 256;   // 256 (K_w = RANK for layers 1,2)
        int b2 = bid - nagg - npool;
        if (b2 < convB) {
            int i = b2 * 256 + tid;
            int n = i / RANK, k = i - n * RANK;
            float sc, sh;
            bn_params(layer, k, gamma, beta, sc, sh);
            g_wh[i] = __float2half_rn(Wnext[(size_t)k * RANK + n] * sc);
        } else {
            int b3 = b2 - convB;         // 0..31
            int n = tid;
            int kpb = RANK / 32;
            int k0 = b3 * kpb;
            float o = 0.f;
            for (int k = k0; k < k0 + kpb; k++) {
                float sc, sh;
                bn_params(layer, k, gamma, beta, sc, sh);
                o = fmaf(sh, Wnext[(size_t)k * RANK + n], o);
            }
            atomicAdd(&g_woff[(layer + 1) * RANK + n], o);
        }
    }
}

// ---------------- mma.sync fp16 GEMM (ldmatrix, 3-stage cp.async) ------------
// CTA 128(M) x 128(N), 256 threads (8 warps 2x4), warp 64x32, K chunk 64.
#define ASTRIDE 72
#define ARB  (ASTRIDE * 2)   // 144 bytes per row
#define SA_ELEM (128 * ASTRIDE)
#define SB_ELEM (128 * ASTRIDE)
#define BUF_BYTES ((SA_ELEM + SB_ELEM) * 2)     // 36864
#define NSTAGE 3
#define GEMM_SMEM (NSTAGE * BUF_BYTES)           // 110592

#define CP16(dst, src) do {                                                \
    uint32_t _d = (uint32_t)__cvta_generic_to_shared(dst);                 \
    asm volatile("cp.async.cg.shared.global [%0], [%1], 16;"               \
                 :: "r"(_d), "l"(src));                                    \
} while (0)

#define MMA16816(C, A, B) \
    asm volatile("mma.sync.aligned.m16n8k16.row.col.f32.f16.f16.f32 " \
        "{%0,%1,%2,%3}, {%4,%5,%6,%7}, {%8,%9}, {%0,%1,%2,%3};" \
        : "+f"((C)[0]), "+f"((C)[1]), "+f"((C)[2]), "+f"((C)[3]) \
        : "r"((A)[0]), "r"((A)[1]), "r"((A)[2]), "r"((A)[3]), \
          "r"((B)[0]), "r"((B)[1]))

#define LDSM_X4(R0, R1, R2, R3, ADDR) \
    asm volatile("ldmatrix.sync.aligned.m8n8.x4.shared.b16 {%0,%1,%2,%3}, [%4];" \
        : "=r"(R0), "=r"(R1), "=r"(R2), "=r"(R3) : "r"(ADDR))

__global__ void __launch_bounds__(256, 2)
k_gemm_mma(int K, const float* __restrict__ bias, int layer) {
    extern __shared__ __align__(16) char smem[];
    uint32_t sbase = (uint32_t)__cvta_generic_to_shared(smem);

    int tid = threadIdx.x;
    int wid = tid >> 5, lid = tid & 31;
    int m0  = blockIdx.x * 128;
    int n0  = blockIdx.y * 128;
    int wm  = (wid & 1) * 64;
    int wn  = (wid >> 1) * 32;
    int lr  = lid >> 2;
    int lc  = lid & 3;

    int t8   = lid >> 3;          // tile index 0..3
    int lrow = lid & 7;
    uint32_t aOff = (uint32_t)((wm + (t8 & 1) * 8 + lrow) * ARB + (t8 >> 1) * 16);
    uint32_t bOff0 = (uint32_t)((wn + (t8 >> 1) * 8 + lrow) * ARB + (t8 & 1) * 16);
    uint32_t bOff1 = bOff0 + (uint32_t)(16 * ARB);

    float c[4][4][4];
    #pragma unroll
    for (int i = 0; i < 4; i++)
        #pragma unroll
        for (int j = 0; j < 4; j++)
            #pragma unroll
            for (int q = 0; q < 4; q++) c[i][j][q] = 0.f;

    auto load_chunk = [&](int kc, int stage) {
        __half* sA = (__half*)(smem + stage * BUF_BYTES);
        __half* sB = sA + SA_ELEM;
        #pragma unroll
        for (int j = 0; j < 4; j++) {
            int i = tid * 4 + j;
            int r = i >> 3, kg = i & 7;
            size_t go = (size_t)(m0 + r) * K + kc + kg * 8;
            CP16(sA + r * ASTRIDE + kg * 8, g_ah + go);
            size_t gob = (size_t)(n0 + r) * K + kc + kg * 8;
            CP16(sB + r * ASTRIDE + kg * 8, g_wh + gob);
        }
        asm volatile("cp.async.commit_group;" ::: "memory");
    };

    int nch = K >> 6;
    load_chunk(0, 0);
    if (nch > 1) load_chunk(64, 1);

    for (int kc = 0; kc < nch; kc++) {
        if (kc + 1 < nch) {
            asm volatile("cp.async.wait_group 1;" ::: "memory");
        } else {
            asm volatile("cp.async.wait_group 0;" ::: "memory");
        }
        __syncthreads();

        if (kc + 2 < nch) load_chunk((kc + 2) << 6, (kc + 2) % NSTAGE);

        uint32_t sAaddr = sbase + (kc % NSTAGE) * BUF_BYTES;
        uint32_t sBaddr = sAaddr + SA_ELEM * 2;

        #pragma unroll
        for (int ks = 0; ks < 4; ks++) {
            uint32_t kso = (uint32_t)(ks * 32);
            uint32_t bb[4][2];
            LDSM_X4(bb[0][0], bb[0][1], bb[1][0], bb[1][1], sBaddr + bOff0 + kso);
            LDSM_X4(bb[2][0], bb[2][1], bb[3][0], bb[3][1], sBaddr + bOff1 + kso);
            #pragma unroll
            for (int fm = 0; fm < 4; fm++) {
                uint32_t aa[4];
                LDSM_X4(aa[0], aa[1], aa[2], aa[3],
                        sAaddr + aOff + (uint32_t)(fm * 16 * ARB) + kso);
                #pragma unroll
                for (int fn = 0; fn < 4; fn++)
                    MMA16816(c[fm][fn], aa, bb[fn]);
            }
        }
        __syncthreads();
    }

    // ---- fused epilogue: y = acc + rho*woff + bias; h = tanh(y) ----
    const float* woff = g_woff + layer * RANK;
    float woffv[8], biasv[8];
    #pragma unroll
    for (int fn = 0; fn < 4; fn++) {
        int col = n0 + wn + fn * 8 + lc * 2;
        woffv[fn * 2]     = woff[col];
        woffv[fn * 2 + 1] = woff[col + 1];
        biasv[fn * 2]     = bias[col];
        biasv[fn * 2 + 1] = bias[col + 1];
    }

    float ts[8], tq[8];
    #pragma unroll
    for (int j = 0; j < 8; j++) { ts[j] = 0.f; tq[j] = 0.f; }

    #pragma unroll
    for (int fm = 0; fm < 4; fm++) {
        int r0 = m0 + wm + fm * 16 + lr;
        int r1 = r0 + 8;
        float rho0 = 0.f, rho1 = 0.f;
        if (r0 < NN) { float d = g_dinv[r0]; rho0 = d * (g_rhop[r0] + d); }
        if (r1 < NN) { float d = g_dinv[r1]; rho1 = d * (g_rhop[r1] + d); }
        #pragma unroll
        for (int fn = 0; fn < 4; fn++) {
            int col = n0 + wn + fn * 8 + lc * 2;
            float w0v = woffv[fn * 2], w1v = woffv[fn * 2 + 1];
            float b0v = biasv[fn * 2], b1v = biasv[fn * 2 + 1];
            if (r0 < NN) {
                float h00 = tanhf(c[fm][fn][0] + rho0 * w0v + b0v);
                float h01 = tanhf(c[fm][fn][1] + rho0 * w1v + b1v);
                *(__half2*)(g_hf16 + (size_t)r0 * RANK + col) = __floats2half2_rn(h00, h01);
                ts[fn * 2] += h00;     tq[fn * 2]     = fmaf(h00, h00, tq[fn * 2]);
                ts[fn * 2 + 1] += h01; tq[fn * 2 + 1] = fmaf(h01, h01, tq[fn * 2 + 1]);
            }
            if (r1 < NN) {
                float h10 = tanhf(c[fm][fn][2] + rho1 * w0v + b0v);
                float h11 = tanhf(c[fm][fn][3] + rho1 * w1v + b1v);
                *(__half2*)(g_hf16 + (size_t)r1 * RANK + col) = __floats2half2_rn(h10, h11);
                ts[fn * 2] += h10;     tq[fn * 2]     = fmaf(h10, h10, tq[fn * 2]);
                ts[fn * 2 + 1] += h11; tq[fn * 2 + 1] = fmaf(h11, h11, tq[fn * 2 + 1]);
            }
        }
    }

    #pragma unroll
    for (int off = 4; off < 32; off <<= 1) {
        #pragma unroll
        for (int j = 0; j < 8; j++) {
            ts[j] += __shfl_xor_sync(0xffffffff, ts[j], off);
            tq[j] += __shfl_xor_sync(0xffffffff, tq[j], off);
        }
    }

    float* red = (float*)smem;   // [0:128) sum, [128:256) sq
    __syncthreads();
    if (tid < 128) { red[tid] = 0.f; red[128 + tid] = 0.f; }
    __syncthreads();
    if (lr == 0) {
        #pragma unroll
        for (int fn = 0; fn < 4; fn++) {
            int lcol = wn + fn * 8 + lc * 2;
            atomicAdd(&red[lcol],           ts[fn * 2]);
            atomicAdd(&red[lcol + 1],       ts[fn * 2 + 1]);
            atomicAdd(&red[128 + lcol],     tq[fn * 2]);
            atomicAdd(&red[128 + lcol + 1], tq[fn * 2 + 1]);
        }
    }
    __syncthreads();
    if (tid < 128) {
        atomicAdd(&g_sum[layer * RANK + n0 + tid],   red[tid]);
        atomicAdd(&g_sumsq[layer * RANK + n0 + tid], red[128 + tid]);
    }
}

// ---------------- launch ----------------------------------------------------
extern "C" void kernel_launch(void* const* d_in, const int* in_sizes, int n_in,
                              void* d_out, int out_size) {
    const float* x     = (const float*)d_in[0];
    const int*   ei    = (const int*)  d_in[1];   // [2, E] int32
    const int*   batch = (const int*)  d_in[2];
    const float* W[3]     = { (const float*)d_in[3],  (const float*)d_in[7],  (const float*)d_in[11] };
    const float* b[3]     = { (const float*)d_in[4],  (const float*)d_in[8],  (const float*)d_in[12] };
    const float* gamma[3] = { (const float*)d_in[5],  (const float*)d_in[9],  (const float*)d_in[13] };
    const float* beta[3]  = { (const float*)d_in[6],  (const float*)d_in[10], (const float*)d_in[14] };
    const int* src = ei;
    const int* dst = ei + EE;
    float* out = (float*)d_out;

    cudaFuncSetAttribute(k_gemm_mma, cudaFuncAttributeMaxDynamicSharedMemorySize, GEMM_SMEM);

    k_init     <<<(NN + 255) / 256, 256>>>();
    k_histconv <<<HISTB + CONVW0B + CONVXB, 256>>>(dst, W[0], x);
    k_dinvscan1<<<98, 256>>>();
    k_scan3gptr<<<98, 256>>>(batch);
    k_scatter  <<<(EE + 255) / 256, 256>>>(src, dst);

    dim3 gemm_grid((NN + 127) / 128, 2);   // 782 x 2
    int ablocks = (NN + ANPB - 1) / ANPB;  // 6250
    int convB   = RANK * RANK / 256 + 32;  // convW + offset blocks

    // layer 0: agg(x) -> gemm
    k_aggpool<<<ablocks, 256>>>(DIN, ablocks, 0, 0, gamma[0], beta[0], out, W[1]);
    k_gemm_mma<<<gemm_grid, 256, GEMM_SMEM>>>(DIN, b[0], 0);

    // layer boundary 0->1: agg(h0) + pool0 + convW1 + woff1
    k_aggpool<<<ablocks + GG + convB, 256>>>(RANK, ablocks, GG, 0,
                                             gamma[0], beta[0], out, W[1]);
    k_gemm_mma<<<gemm_grid, 256, GEMM_SMEM>>>(RANK, b[1], 1);

    // layer boundary 1->2
    k_aggpool<<<ablocks + GG + convB, 256>>>(RANK, ablocks, GG, 1,
                                             gamma[1], beta[1],
                                             out + (size_t)GG * RANK, W[2]);
    k_gemm_mma<<<gemm_grid, 256, GEMM_SMEM>>>(RANK, b[2], 2);

    // final pool (layer 2)
    k_aggpool<<<GG, 256>>>(RANK, 0, GG, 2, gamma[2], beta[2],
                           out + (size_t)2 * GG * RANK, W[2]);
}

// round 14
// speedup vs baseline: 1.0001x; 1.0001x over previous
#include <cuda_runtime.h>
#include <cuda_fp16.h>
#include <math.h>
#include <stdint.h>

#define NN   100000
#define NPAD 100096          // 782 * 128
#define EE   400000
#define GG   2048
#define DIN  128
#define RANK 256

// ---------------- scratch (device globals: no allocations allowed) ----------
__device__ __half g_hf16[NPAD * RANK];   // h (tanh out) fp16; also x fp16 (lda=K)
__device__ __half g_ah [NPAD * RANK];    // Agg(h) fp16 (lda = K)
__device__ __half g_wh [RANK * RANK];    // (scale-folded) W^T fp16  [n][k]
__device__ float g_woff[3 * RANK];       // rank-1 BN offset per layer
__device__ float g_rhop[NN];
__device__ int   g_cnt   [NN];
__device__ int   g_cursor[NN];
__device__ int   g_rowptr[NN + 1];
__device__ float g_dinv  [NN];
__device__ int   g_esrc[EE];
__device__ float g_ew  [EE];
__device__ int   g_gptr[GG + 1];
__device__ float g_sum  [3 * RANK];      // per-layer BN stats
__device__ float g_sumsq[3 * RANK];
__device__ int   g_part[128];

// ---------------- BN param helper -------------------------------------------
__device__ __forceinline__ void bn_params(int layer, int c,
                                          const float* gamma, const float* beta,
                                          float& sc, float& sh) {
    float mu  = g_sum[layer * RANK + c]   * (1.0f / NN);
    float var = g_sumsq[layer * RANK + c] * (1.0f / NN) - mu * mu;
    sc = gamma[c] * rsqrtf(var + 1e-5f);
    sh = beta[c] - mu * sc;
}

// ---------------- graph preprocessing ----------------------------------------
__global__ void k_init() {
    int i = blockIdx.x * blockDim.x + threadIdx.x;
    if (i < NN) { g_cnt[i] = 0; g_cursor[i] = 0; g_rhop[i] = 0.f; }
    if (i < 3 * RANK) { g_sum[i] = 0.f; g_sumsq[i] = 0.f; g_woff[i] = 0.f; }
}

// hist + convW0 + x->fp16, one launch (independent block ranges)
#define HISTB 1563            // ceil(EE/256)
#define CONVW0B (RANK * DIN / 256)   // 128
#define CONVXB (NN * DIN / 4 / 256)  // 12500
__global__ void k_histconv(const int* __restrict__ dst,
                           const float* __restrict__ W0,
                           const float* __restrict__ x) {
    int b = blockIdx.x;
    if (b < HISTB) {
        int e = b * 256 + threadIdx.x;
        if (e < EE) atomicAdd(&g_cnt[dst[e]], 1);
    } else if (b < HISTB + CONVW0B) {
        int i = (b - HISTB) * 256 + threadIdx.x;     // over RANK*DIN
        int n = i / DIN, k = i - n * DIN;
        g_wh[i] = __float2half_rn(W0[(size_t)k * RANK + n]);
    } else {
        int i4 = (b - HISTB - CONVW0B) * 256 + threadIdx.x;
        if (i4 < NN * DIN / 4) {
            float4 v = ((const float4*)x)[i4];
            __half2 a = __floats2half2_rn(v.x, v.y);
            __half2 c = __floats2half2_rn(v.z, v.w);
            *(uint2*)(g_hf16 + (size_t)i4 * 4) = make_uint2(*(uint32_t*)&a, *(uint32_t*)&c);
        }
    }
}

// dinv + scan phase 1 (block sums)
__global__ void k_dinvscan1() {
    __shared__ int sm[256];
    int b = blockIdx.x, t = threadIdx.x;
    if (b == 0 && t == 0) g_rowptr[NN] = EE;
    int base = b * 1024 + t * 4;
    int s = 0;
    #pragma unroll
    for (int j = 0; j < 4; j++) {
        int i = base + j;
        if (i < NN) {
            int c = g_cnt[i];
            s += c;
            g_dinv[i] = rsqrtf((float)(c + 1));
        }
    }
    sm[t] = s; __syncthreads();
    for (int off = 128; off > 0; off >>= 1) {
        if (t < off) sm[t] += sm[t + off];
        __syncthreads();
    }
    if (t == 0) g_part[b] = sm[0];
}

// scan phase 2 (in-block re-scan of partials) + phase 3 + gptr
__global__ void k_scan3gptr(const int* __restrict__ batch) {
    __shared__ int sm[256];
    __shared__ int sp[128];
    int b = blockIdx.x, t = threadIdx.x;

    if (t < 128) sp[t] = (t < 98) ? g_part[t] : 0;
    __syncthreads();
    for (int off = 1; off < 128; off <<= 1) {
        int u = (t >= off && t < 128) ? sp[t - off] : 0;
        __syncthreads();
        if (t < 128) sp[t] += u;
        __syncthreads();
    }
    int blockPrefix = (b > 0) ? sp[b - 1] : 0;   // exclusive

    int base = b * 1024 + t * 4;
    int v[4]; int s = 0;
    #pragma unroll
    for (int j = 0; j < 4; j++) { int i = base + j; v[j] = (i < NN) ? g_cnt[i] : 0; s += v[j]; }
    sm[t] = s; __syncthreads();
    for (int off = 1; off < 256; off <<= 1) {
        int u = (t >= off) ? sm[t - off] : 0;
        __syncthreads();
        sm[t] += u;
        __syncthreads();
    }
    int off0 = blockPrefix + (sm[t] - s);
    int run = 0;
    #pragma unroll
    for (int j = 0; j < 4; j++) {
        int i = base + j;
        if (i < NN) {
            g_rowptr[i] = off0 + run;
            int bi = batch[i];
            if (i == 0) {
                for (int g = 0; g <= bi; g++) g_gptr[g] = 0;
            } else {
                int bp = batch[i - 1];
                for (int g = bp + 1; g <= bi; g++) g_gptr[g] = i;
            }
            if (i == NN - 1) {
                for (int g = bi + 1; g <= GG; g++) g_gptr[g] = NN;
            }
        }
        run += v[j];
    }
}

__global__ void k_scatter(const int* __restrict__ src, const int* __restrict__ dst) {
    int e = blockIdx.x * blockDim.x + threadIdx.x;
    if (e >= EE) return;
    int s = src[e], d = dst[e];
    int pos = g_rowptr[d] + atomicAdd(&g_cursor[d], 1);
    float ds = g_dinv[s];
    g_esrc[pos] = s;
    g_ew[pos]   = ds * g_dinv[d];
    atomicAdd(&g_rhop[d], ds);
}

// ---------------- fused per-layer-boundary kernel ----------------------------
// Block order: [pool (npool)] [convW+woff (nconv)] [aggregation (rest)]
// (short work first so it hides inside the agg waves instead of the tail)
#define ANPB 16
__global__ void __launch_bounds__(256)
k_aggpool(int K, int npool, int nconv, int layer,
          const float* __restrict__ gamma, const float* __restrict__ beta,
          float* __restrict__ out, const float* __restrict__ Wnext) {
    int bid = blockIdx.x;
    int tid = threadIdx.x;

    if (bid < npool) {
        // ---- pool (scalar per-column, x2 row unroll) ----
        int g = bid, c = tid;
        int beg = g_gptr[g], end = g_gptr[g + 1];
        float sc, sh;
        bn_params(layer, c, gamma, beta, sc, sh);
        float m0 = -INFINITY, m1 = -INFINITY;
        int r = beg;
        for (; r + 2 <= end; r += 2) {
            m0 = fmaxf(m0, __half2float(g_hf16[(size_t)r * RANK + c]));
            m1 = fmaxf(m1, __half2float(g_hf16[(size_t)(r + 1) * RANK + c]));
        }
        if (r < end) m0 = fmaxf(m0, __half2float(g_hf16[(size_t)r * RANK + c]));
        float m = fmaxf(m0, m1);
        out[(size_t)g * RANK + c] = (end > beg) ? fmaf(sc, m, sh) : 0.0f;
    } else if (bid < npool + nconv) {
        int convB = RANK * RANK / 256;   // 256 (K_w = RANK for layers 1,2)
        int b2 = bid - npool;
        if (b2 < convB) {
            // ---- convW for layer+1, scale-folded by stats[layer] ----
            int i = b2 * 256 + tid;
            int n = i / RANK, k = i - n * RANK;
            float sc, sh;
            bn_params(layer, k, gamma, beta, sc, sh);
            g_wh[i] = __float2half_rn(Wnext[(size_t)k * RANK + n] * sc);
        } else {
            // ---- rank-1 offset for layer+1 ----
            int b3 = b2 - convB;         // 0..31
            int n = tid;
            int kpb = RANK / 32;
            int k0 = b3 * kpb;
            float o = 0.f;
            for (int k = k0; k < k0 + kpb; k++) {
                float sc, sh;
                bn_params(layer, k, gamma, beta, sc, sh);
                o = fmaf(sh, Wnext[(size_t)k * RANK + n], o);
            }
            atomicAdd(&g_woff[(layer + 1) * RANK + n], o);
        }
    } else {
        // ---- aggregation (x2 unroll; mean degree ~4) ----
        int abid = bid - npool - nconv;
        int ncg  = K >> 3;
        int cg   = (tid & (ncg - 1)) * 8;
        int sub  = tid / ncg;
        int nsub = 256 / ncg;
        int v0   = abid * ANPB;

        for (int n = sub; n < ANPB; n += nsub) {
            int v = v0 + n;
            if (v >= NN) break;
            int beg = g_rowptr[v], end = g_rowptr[v + 1];
            float di = g_dinv[v];
            float w0 = di * di;

            float acc[8];
            {
                uint4 u = *(const uint4*)(g_hf16 + (size_t)v * K + cg);
                const __half2* hp = (const __half2*)&u;
                #pragma unroll
                for (int j = 0; j < 4; j++) {
                    float2 f = __half22float2(hp[j]);
                    acc[2 * j]     = w0 * f.x;
                    acc[2 * j + 1] = w0 * f.y;
                }
            }
            int e = beg;
            for (; e + 2 <= end; e += 2) {
                float w1 = g_ew[e], w2 = g_ew[e + 1];
                int   s1 = g_esrc[e], s2 = g_esrc[e + 1];
                uint4 u1 = *(const uint4*)(g_hf16 + (size_t)s1 * K + cg);
                uint4 u2 = *(const uint4*)(g_hf16 + (size_t)s2 * K + cg);
                const __half2* h1 = (const __half2*)&u1;
                const __half2* h2 = (const __half2*)&u2;
                #pragma unroll
                for (int j = 0; j < 4; j++) {
                    float2 f1 = __half22float2(h1[j]);
                    float2 f2 = __half22float2(h2[j]);
                    acc[2 * j]     = fmaf(w1, f1.x, acc[2 * j]);
                    acc[2 * j + 1] = fmaf(w1, f1.y, acc[2 * j + 1]);
                    acc[2 * j]     = fmaf(w2, f2.x, acc[2 * j]);
                    acc[2 * j + 1] = fmaf(w2, f2.y, acc[2 * j + 1]);
                }
            }
            for (; e < end; e++) {
                float w = g_ew[e];
                int   s = g_esrc[e];
                uint4 u = *(const uint4*)(g_hf16 + (size_t)s * K + cg);
                const __half2* hp = (const __half2*)&u;
                #pragma unroll
                for (int j = 0; j < 4; j++) {
                    float2 f = __half22float2(hp[j]);
                    acc[2 * j]     = fmaf(w, f.x, acc[2 * j]);
                    acc[2 * j + 1] = fmaf(w, f.y, acc[2 * j + 1]);
                }
            }

            __align__(16) __half o[8];
            #pragma unroll
            for (int j = 0; j < 8; j++) o[j] = __float2half_rn(acc[j]);
            *(uint4*)(g_ah + (size_t)v * K + cg) = *(uint4*)o;
        }
    }
}

// ---------------- mma.sync fp16 GEMM (ldmatrix, 2-stage cp.async) ------------
// CTA 128(M) x 128(N), 256 threads (8 warps 2x4), warp 64x32, K chunk 64.
#define ASTRIDE 72
#define ARB  (ASTRIDE * 2)   // 144 bytes per row
#define SA_ELEM (128 * ASTRIDE)
#define SB_ELEM (128 * ASTRIDE)
#define BUF_BYTES ((SA_ELEM + SB_ELEM) * 2)     // 36864
#define GEMM_SMEM (2 * BUF_BYTES)                // 73728

#define CP16(dst, src) do {                                                \
    uint32_t _d = (uint32_t)__cvta_generic_to_shared(dst);                 \
    asm volatile("cp.async.cg.shared.global [%0], [%1], 16;"               \
                 :: "r"(_d), "l"(src));                                    \
} while (0)

#define MMA16816(C, A, B) \
    asm volatile("mma.sync.aligned.m16n8k16.row.col.f32.f16.f16.f32 " \
        "{%0,%1,%2,%3}, {%4,%5,%6,%7}, {%8,%9}, {%0,%1,%2,%3};" \
        : "+f"((C)[0]), "+f"((C)[1]), "+f"((C)[2]), "+f"((C)[3]) \
        : "r"((A)[0]), "r"((A)[1]), "r"((A)[2]), "r"((A)[3]), \
          "r"((B)[0]), "r"((B)[1]))

#define LDSM_X4(R0, R1, R2, R3, ADDR) \
    asm volatile("ldmatrix.sync.aligned.m8n8.x4.shared.b16 {%0,%1,%2,%3}, [%4];" \
        : "=r"(R0), "=r"(R1), "=r"(R2), "=r"(R3) : "r"(ADDR))

__global__ void __launch_bounds__(256, 2)
k_gemm_mma(int K, const float* __restrict__ bias, int layer) {
    extern __shared__ __align__(16) char smem[];
    uint32_t sbase = (uint32_t)__cvta_generic_to_shared(smem);

    int tid = threadIdx.x;
    int wid = tid >> 5, lid = tid & 31;
    int m0  = blockIdx.x * 128;
    int n0  = blockIdx.y * 128;
    int wm  = (wid & 1) * 64;
    int wn  = (wid >> 1) * 32;
    int lr  = lid >> 2;
    int lc  = lid & 3;

    int t8   = lid >> 3;          // tile index 0..3
    int lrow = lid & 7;
    uint32_t aOff = (uint32_t)((wm + (t8 & 1) * 8 + lrow) * ARB + (t8 >> 1) * 16);
    uint32_t bOff0 = (uint32_t)((wn + (t8 >> 1) * 8 + lrow) * ARB + (t8 & 1) * 16);
    uint32_t bOff1 = bOff0 + (uint32_t)(16 * ARB);

    float c[4][4][4];
    #pragma unroll
    for (int i = 0; i < 4; i++)
        #pragma unroll
        for (int j = 0; j < 4; j++)
            #pragma unroll
            for (int q = 0; q < 4; q++) c[i][j][q] = 0.f;

    auto load_chunk = [&](int kc, char* base) {
        __half* sA = (__half*)base;
        __half* sB = sA + SA_ELEM;
        #pragma unroll
        for (int j = 0; j < 4; j++) {
            int i = tid * 4 + j;
            int r = i >> 3, kg = i & 7;
            size_t go = (size_t)(m0 + r) * K + kc + kg * 8;
            CP16(sA + r * ASTRIDE + kg * 8, g_ah + go);
            size_t gob = (size_t)(n0 + r) * K + kc + kg * 8;
            CP16(sB + r * ASTRIDE + kg * 8, g_wh + gob);
        }
        asm volatile("cp.async.commit_group;" ::: "memory");
    };

    int nch = K >> 6;
    load_chunk(0, smem);

    for (int kc = 0; kc < nch; kc++) {
        if (kc + 1 < nch) {
            load_chunk((kc + 1) << 6, smem + ((kc + 1) & 1) * BUF_BYTES);
            asm volatile("cp.async.wait_group 1;" ::: "memory");
        } else {
            asm volatile("cp.async.wait_group 0;" ::: "memory");
        }
        __syncthreads();

        uint32_t sAaddr = sbase + (kc & 1) * BUF_BYTES;
        uint32_t sBaddr = sAaddr + SA_ELEM * 2;

        #pragma unroll
        for (int ks = 0; ks < 4; ks++) {
            uint32_t kso = (uint32_t)(ks * 32);
            uint32_t bb[4][2];
            LDSM_X4(bb[0][0], bb[0][1], bb[1][0], bb[1][1], sBaddr + bOff0 + kso);
            LDSM_X4(bb[2][0], bb[2][1], bb[3][0], bb[3][1], sBaddr + bOff1 + kso);
            #pragma unroll
            for (int fm = 0; fm < 4; fm++) {
                uint32_t aa[4];
                LDSM_X4(aa[0], aa[1], aa[2], aa[3],
                        sAaddr + aOff + (uint32_t)(fm * 16 * ARB) + kso);
                #pragma unroll
                for (int fn = 0; fn < 4; fn++)
                    MMA16816(c[fm][fn], aa, bb[fn]);
            }
        }
        __syncthreads();
    }

    // ---- fused epilogue: y = acc + rho*woff + bias; h = tanh(y) ----
    const float* woff = g_woff + layer * RANK;
    float woffv[8], biasv[8];
    #pragma unroll
    for (int fn = 0; fn < 4; fn++) {
        int col = n0 + wn + fn * 8 + lc * 2;
        woffv[fn * 2]     = woff[col];
        woffv[fn * 2 + 1] = woff[col + 1];
        biasv[fn * 2]     = bias[col];
        biasv[fn * 2 + 1] = bias[col + 1];
    }

    float ts[8], tq[8];
    #pragma unroll
    for (int j = 0; j < 8; j++) { ts[j] = 0.f; tq[j] = 0.f; }

    #pragma unroll
    for (int fm = 0; fm < 4; fm++) {
        int r0 = m0 + wm + fm * 16 + lr;
        int r1 = r0 + 8;
        float rho0 = 0.f, rho1 = 0.f;
        if (r0 < NN) { float d = g_dinv[r0]; rho0 = d * (g_rhop[r0] + d); }
        if (r1 < NN) { float d = g_dinv[r1]; rho1 = d * (g_rhop[r1] + d); }
        #pragma unroll
        for (int fn = 0; fn < 4; fn++) {
            int col = n0 + wn + fn * 8 + lc * 2;
            float w0v = woffv[fn * 2], w1v = woffv[fn * 2 + 1];
            float b0v = biasv[fn * 2], b1v = biasv[fn * 2 + 1];
            if (r0 < NN) {
                float h00 = tanhf(c[fm][fn][0] + rho0 * w0v + b0v);
                float h01 = tanhf(c[fm][fn][1] + rho0 * w1v + b1v);
                *(__half2*)(g_hf16 + (size_t)r0 * RANK + col) = __floats2half2_rn(h00, h01);
                ts[fn * 2] += h00;     tq[fn * 2]     = fmaf(h00, h00, tq[fn * 2]);
                ts[fn * 2 + 1] += h01; tq[fn * 2 + 1] = fmaf(h01, h01, tq[fn * 2 + 1]);
            }
            if (r1 < NN) {
                float h10 = tanhf(c[fm][fn][2] + rho1 * w0v + b0v);
                float h11 = tanhf(c[fm][fn][3] + rho1 * w1v + b1v);
                *(__half2*)(g_hf16 + (size_t)r1 * RANK + col) = __floats2half2_rn(h10, h11);
                ts[fn * 2] += h10;     tq[fn * 2]     = fmaf(h10, h10, tq[fn * 2]);
                ts[fn * 2 + 1] += h11; tq[fn * 2 + 1] = fmaf(h11, h11, tq[fn * 2 + 1]);
            }
        }
    }

    #pragma unroll
    for (int off = 4; off < 32; off <<= 1) {
        #pragma unroll
        for (int j = 0; j < 8; j++) {
            ts[j] += __shfl_xor_sync(0xffffffff, ts[j], off);
            tq[j] += __shfl_xor_sync(0xffffffff, tq[j], off);
        }
    }

    float* red = (float*)smem;   // [0:128) sum, [128:256) sq
    __syncthreads();
    if (tid < 128) { red[tid] = 0.f; red[128 + tid] = 0.f; }
    __syncthreads();
    if (lr == 0) {
        #pragma unroll
        for (int fn = 0; fn < 4; fn++) {
            int lcol = wn + fn * 8 + lc * 2;
            atomicAdd(&red[lcol],           ts[fn * 2]);
            atomicAdd(&red[lcol + 1],       ts[fn * 2 + 1]);
            atomicAdd(&red[128 + lcol],     tq[fn * 2]);
            atomicAdd(&red[128 + lcol + 1], tq[fn * 2 + 1]);
        }
    }
    __syncthreads();
    if (tid < 128) {
        atomicAdd(&g_sum[layer * RANK + n0 + tid],   red[tid]);
        atomicAdd(&g_sumsq[layer * RANK + n0 + tid], red[128 + tid]);
    }
}

// ---------------- launch ----------------------------------------------------
extern "C" void kernel_launch(void* const* d_in, const int* in_sizes, int n_in,
                              void* d_out, int out_size) {
    const float* x     = (const float*)d_in[0];
    const int*   ei    = (const int*)  d_in[1];   // [2, E] int32
    const int*   batch = (const int*)  d_in[2];
    const float* W[3]     = { (const float*)d_in[3],  (const float*)d_in[7],  (const float*)d_in[11] };
    const float* b[3]     = { (const float*)d_in[4],  (const float*)d_in[8],  (const float*)d_in[12] };
    const float* gamma[3] = { (const float*)d_in[5],  (const float*)d_in[9],  (const float*)d_in[13] };
    const float* beta[3]  = { (const float*)d_in[6],  (const float*)d_in[10], (const float*)d_in[14] };
    const int* src = ei;
    const int* dst = ei + EE;
    float* out = (float*)d_out;

    cudaFuncSetAttribute(k_gemm_mma, cudaFuncAttributeMaxDynamicSharedMemorySize, GEMM_SMEM);

    k_init     <<<(NN + 255) / 256, 256>>>();
    k_histconv <<<HISTB + CONVW0B + CONVXB, 256>>>(dst, W[0], x);
    k_dinvscan1<<<98, 256>>>();
    k_scan3gptr<<<98, 256>>>(batch);
    k_scatter  <<<(EE + 255) / 256, 256>>>(src, dst);

    dim3 gemm_grid((NN + 127) / 128, 2);   // 782 x 2
    int ablocks = (NN + ANPB - 1) / ANPB;  // 6250
    int nconv   = RANK * RANK / 256 + 32;  // 288 convW + offset blocks

    // layer 0: agg(x) -> gemm      (npool=0, nconv=0)
    k_aggpool<<<ablocks, 256>>>(DIN, 0, 0, 0, gamma[0], beta[0], out, W[1]);
    k_gemm_mma<<<gemm_grid, 256, GEMM_SMEM>>>(DIN, b[0], 0);

    // layer boundary 0->1: pool0 + convW1 + woff1 + agg(h0)  (short work first)
    k_aggpool<<<GG + nconv + ablocks, 256>>>(RANK, GG, nconv, 0,
                                             gamma[0], beta[0], out, W[1]);
    k_gemm_mma<<<gemm_grid, 256, GEMM_SMEM>>>(RANK, b[1], 1);

    // layer boundary 1->2
    k_aggpool<<<GG + nconv + ablocks, 256>>>(RANK, GG, nconv, 1,
                                             gamma[1], beta[1],
                                             out + (size_t)GG * RANK, W[2]);
    k_gemm_mma<<<gemm_grid, 256, GEMM_SMEM>>>(RANK, b[2], 2);

    // final pool (layer 2)
    k_aggpool<<<GG, 256>>>(RANK, GG, 0, 2, gamma[2], beta[2],
                           out + (size_t)2 * GG * RANK, W[2]);
}

// round 15
// speedup vs baseline: 1.0638x; 1.0637x over previous
#include <cuda_runtime.h>
#include <cuda_fp16.h>
#include <math.h>
#include <stdint.h>

#define NN   100000
#define NPAD 100096          // 782 * 128
#define EE   400000
#define GG   2048
#define DIN  128
#define RANK 256

// ---------------- scratch (device globals: no allocations allowed) ----------
__device__ __half g_hf16[NPAD * RANK];   // h (tanh out) fp16; also x fp16 (lda=K)
__device__ __half g_ah [NPAD * RANK];    // Agg(h) fp16 (lda = K)
__device__ __half g_wh [RANK * RANK];    // (scale-folded) W^T fp16  [n][k]
__device__ float g_woff[3 * RANK];       // rank-1 BN offset per layer
__device__ float g_rhop[NN];
__device__ int   g_cnt   [NN];
__device__ int   g_cursor[NN];
__device__ int   g_rowptr[NN + 1];
__device__ float g_dinv  [NN];
__device__ int   g_esrc[EE];
__device__ float g_ew  [EE];
__device__ int   g_gptr[GG + 1];
__device__ float g_sum  [3 * RANK];      // per-layer BN stats
__device__ float g_sumsq[3 * RANK];
__device__ int   g_part[128];

__device__ __forceinline__ float tanh_fast(float x) {
    float y;
    asm("tanh.approx.f32 %0, %1;" : "=f"(y) : "f"(x));
    return y;
}

// ---------------- BN param helper -------------------------------------------
__device__ __forceinline__ void bn_params(int layer, int c,
                                          const float* gamma, const float* beta,
                                          float& sc, float& sh) {
    float mu  = g_sum[layer * RANK + c]   * (1.0f / NN);
    float var = g_sumsq[layer * RANK + c] * (1.0f / NN) - mu * mu;
    sc = gamma[c] * rsqrtf(var + 1e-5f);
    sh = beta[c] - mu * sc;
}

// ---------------- graph preprocessing ----------------------------------------
__global__ void k_init() {
    int i = blockIdx.x * blockDim.x + threadIdx.x;
    if (i < NN) { g_cnt[i] = 0; g_cursor[i] = 0; g_rhop[i] = 0.f; }
    if (i < 3 * RANK) { g_sum[i] = 0.f; g_sumsq[i] = 0.f; g_woff[i] = 0.f; }
}

// hist + convW0 + x->fp16, one launch (independent block ranges)
#define HISTB 1563            // ceil(EE/256)
#define CONVW0B (RANK * DIN / 256)   // 128
#define CONVXB (NN * DIN / 4 / 256)  // 12500
__global__ void k_histconv(const int* __restrict__ dst,
                           const float* __restrict__ W0,
                           const float* __restrict__ x) {
    int b = blockIdx.x;
    if (b < HISTB) {
        int e = b * 256 + threadIdx.x;
        if (e < EE) atomicAdd(&g_cnt[dst[e]], 1);
    } else if (b < HISTB + CONVW0B) {
        int i = (b - HISTB) * 256 + threadIdx.x;     // over RANK*DIN
        int n = i / DIN, k = i - n * DIN;
        g_wh[i] = __float2half_rn(W0[(size_t)k * RANK + n]);
    } else {
        int i4 = (b - HISTB - CONVW0B) * 256 + threadIdx.x;
        if (i4 < NN * DIN / 4) {
            float4 v = ((const float4*)x)[i4];
            __half2 a = __floats2half2_rn(v.x, v.y);
            __half2 c = __floats2half2_rn(v.z, v.w);
            *(uint2*)(g_hf16 + (size_t)i4 * 4) = make_uint2(*(uint32_t*)&a, *(uint32_t*)&c);
        }
    }
}

// dinv + scan phase 1 (block sums)
__global__ void k_dinvscan1() {
    __shared__ int sm[256];
    int b = blockIdx.x, t = threadIdx.x;
    if (b == 0 && t == 0) g_rowptr[NN] = EE;
    int base = b * 1024 + t * 4;
    int s = 0;
    #pragma unroll
    for (int j = 0; j < 4; j++) {
        int i = base + j;
        if (i < NN) {
            int c = g_cnt[i];
            s += c;
            g_dinv[i] = rsqrtf((float)(c + 1));
        }
    }
    sm[t] = s; __syncthreads();
    for (int off = 128; off > 0; off >>= 1) {
        if (t < off) sm[t] += sm[t + off];
        __syncthreads();
    }
    if (t == 0) g_part[b] = sm[0];
}

// scan phase 2 (in-block re-scan of partials) + phase 3 + gptr
__global__ void k_scan3gptr(const int* __restrict__ batch) {
    __shared__ int sm[256];
    __shared__ int sp[128];
    int b = blockIdx.x, t = threadIdx.x;

    if (t < 128) sp[t] = (t < 98) ? g_part[t] : 0;
    __syncthreads();
    for (int off = 1; off < 128; off <<= 1) {
        int u = (t >= off && t < 128) ? sp[t - off] : 0;
        __syncthreads();
        if (t < 128) sp[t] += u;
        __syncthreads();
    }
    int blockPrefix = (b > 0) ? sp[b - 1] : 0;   // exclusive

    int base = b * 1024 + t * 4;
    int v[4]; int s = 0;
    #pragma unroll
    for (int j = 0; j < 4; j++) { int i = base + j; v[j] = (i < NN) ? g_cnt[i] : 0; s += v[j]; }
    sm[t] = s; __syncthreads();
    for (int off = 1; off < 256; off <<= 1) {
        int u = (t >= off) ? sm[t - off] : 0;
        __syncthreads();
        sm[t] += u;
        __syncthreads();
    }
    int off0 = blockPrefix + (sm[t] - s);
    int run = 0;
    #pragma unroll
    for (int j = 0; j < 4; j++) {
        int i = base + j;
        if (i < NN) {
            g_rowptr[i] = off0 + run;
            int bi = batch[i];
            if (i == 0) {
                for (int g = 0; g <= bi; g++) g_gptr[g] = 0;
            } else {
                int bp = batch[i - 1];
                for (int g = bp + 1; g <= bi; g++) g_gptr[g] = i;
            }
            if (i == NN - 1) {
                for (int g = bi + 1; g <= GG; g++) g_gptr[g] = NN;
            }
        }
        run += v[j];
    }
}

__global__ void k_scatter(const int* __restrict__ src, const int* __restrict__ dst) {
    int e = blockIdx.x * blockDim.x + threadIdx.x;
    if (e >= EE) return;
    int s = src[e], d = dst[e];
    int pos = g_rowptr[d] + atomicAdd(&g_cursor[d], 1);
    float ds = g_dinv[s];
    g_esrc[pos] = s;
    g_ew[pos]   = ds * g_dinv[d];
    atomicAdd(&g_rhop[d], ds);
}

// ---------------- fused per-layer-boundary kernel ----------------------------
// blocks [0,nagg): aggregation (K cols) h->g_ah
// blocks [nagg, nagg+npool): global max pool of `layer`
// blocks [nagg+npool, ...): convert W_next + rank-1 offset
#define ANPB 16
__global__ void __launch_bounds__(256)
k_aggpool(int K, int nagg, int npool, int layer,
          const float* __restrict__ gamma, const float* __restrict__ beta,
          float* __restrict__ out, const float* __restrict__ Wnext) {
    int bid = blockIdx.x;
    int tid = threadIdx.x;

    if (bid < nagg) {
        // ---- aggregation (x2 unroll; mean degree ~4) ----
        int ncg  = K >> 3;
        int cg   = (tid & (ncg - 1)) * 8;
        int sub  = tid / ncg;
        int nsub = 256 / ncg;
        int v0   = bid * ANPB;

        for (int n = sub; n < ANPB; n += nsub) {
            int v = v0 + n;
            if (v >= NN) break;
            int beg = g_rowptr[v], end = g_rowptr[v + 1];
            float di = g_dinv[v];
            float w0 = di * di;

            float acc[8];
            {
                uint4 u = *(const uint4*)(g_hf16 + (size_t)v * K + cg);
                const __half2* hp = (const __half2*)&u;
                #pragma unroll
                for (int j = 0; j < 4; j++) {
                    float2 f = __half22float2(hp[j]);
                    acc[2 * j]     = w0 * f.x;
                    acc[2 * j + 1] = w0 * f.y;
                }
            }
            int e = beg;
            for (; e + 2 <= end; e += 2) {
                float w1 = g_ew[e], w2 = g_ew[e + 1];
                int   s1 = g_esrc[e], s2 = g_esrc[e + 1];
                uint4 u1 = *(const uint4*)(g_hf16 + (size_t)s1 * K + cg);
                uint4 u2 = *(const uint4*)(g_hf16 + (size_t)s2 * K + cg);
                const __half2* h1 = (const __half2*)&u1;
                const __half2* h2 = (const __half2*)&u2;
                #pragma unroll
                for (int j = 0; j < 4; j++) {
                    float2 f1 = __half22float2(h1[j]);
                    float2 f2 = __half22float2(h2[j]);
                    acc[2 * j]     = fmaf(w1, f1.x, acc[2 * j]);
                    acc[2 * j + 1] = fmaf(w1, f1.y, acc[2 * j + 1]);
                    acc[2 * j]     = fmaf(w2, f2.x, acc[2 * j]);
                    acc[2 * j + 1] = fmaf(w2, f2.y, acc[2 * j + 1]);
                }
            }
            for (; e < end; e++) {
                float w = g_ew[e];
                int   s = g_esrc[e];
                uint4 u = *(const uint4*)(g_hf16 + (size_t)s * K + cg);
                const __half2* hp = (const __half2*)&u;
                #pragma unroll
                for (int j = 0; j < 4; j++) {
                    float2 f = __half22float2(hp[j]);
                    acc[2 * j]     = fmaf(w, f.x, acc[2 * j]);
                    acc[2 * j + 1] = fmaf(w, f.y, acc[2 * j + 1]);
                }
            }

            __align__(16) __half o[8];
            #pragma unroll
            for (int j = 0; j < 8; j++) o[j] = __float2half_rn(acc[j]);
            *(uint4*)(g_ah + (size_t)v * K + cg) = *(uint4*)o;
        }
    } else if (bid < nagg + npool) {
        // ---- pool (scalar per-column, x2 row unroll) ----
        int g = bid - nagg, c = tid;
        int beg = g_gptr[g], end = g_gptr[g + 1];
        float sc, sh;
        bn_params(layer, c, gamma, beta, sc, sh);
        float m0 = -INFINITY, m1 = -INFINITY;
        int r = beg;
        for (; r + 2 <= end; r += 2) {
            m0 = fmaxf(m0, __half2float(g_hf16[(size_t)r * RANK + c]));
            m1 = fmaxf(m1, __half2float(g_hf16[(size_t)(r + 1) * RANK + c]));
        }
        if (r < end) m0 = fmaxf(m0, __half2float(g_hf16[(size_t)r * RANK + c]));
        float m = fmaxf(m0, m1);
        out[(size_t)g * RANK + c] = (end > beg) ? fmaf(sc, m, sh) : 0.0f;
    } else {
        int convB = RANK * RANK / 256;   // 256 (K_w = RANK for layers 1,2)
        int b2 = bid - nagg - npool;
        if (b2 < convB) {
            // ---- convW for layer+1, scale-folded by stats[layer] ----
            int i = b2 * 256 + tid;
            int n = i / RANK, k = i - n * RANK;
            float sc, sh;
            bn_params(layer, k, gamma, beta, sc, sh);
            g_wh[i] = __float2half_rn(Wnext[(size_t)k * RANK + n] * sc);
        } else {
            // ---- rank-1 offset for layer+1 ----
            int b3 = b2 - convB;         // 0..31
            int n = tid;
            int kpb = RANK / 32;
            int k0 = b3 * kpb;
            float o = 0.f;
            for (int k = k0; k < k0 + kpb; k++) {
                float sc, sh;
                bn_params(layer, k, gamma, beta, sc, sh);
                o = fmaf(sh, Wnext[(size_t)k * RANK + n], o);
            }
            atomicAdd(&g_woff[(layer + 1) * RANK + n], o);
        }
    }
}

// ---------------- mma.sync fp16 GEMM (ldmatrix, 2-stage cp.async) ------------
// CTA 128(M) x 128(N), 256 threads (8 warps 2x4), warp 64x32, K chunk 64.
#define ASTRIDE 72
#define ARB  (ASTRIDE * 2)   // 144 bytes per row
#define SA_ELEM (128 * ASTRIDE)
#define SB_ELEM (128 * ASTRIDE)
#define BUF_BYTES ((SA_ELEM + SB_ELEM) * 2)     // 36864
#define GEMM_SMEM (2 * BUF_BYTES)                // 73728

#define CP16(dst, src) do {                                                \
    uint32_t _d = (uint32_t)__cvta_generic_to_shared(dst);                 \
    asm volatile("cp.async.cg.shared.global [%0], [%1], 16;"               \
                 :: "r"(_d), "l"(src));                                    \
} while (0)

#define MMA16816(C, A, B) \
    asm volatile("mma.sync.aligned.m16n8k16.row.col.f32.f16.f16.f32 " \
        "{%0,%1,%2,%3}, {%4,%5,%6,%7}, {%8,%9}, {%0,%1,%2,%3};" \
        : "+f"((C)[0]), "+f"((C)[1]), "+f"((C)[2]), "+f"((C)[3]) \
        : "r"((A)[0]), "r"((A)[1]), "r"((A)[2]), "r"((A)[3]), \
          "r"((B)[0]), "r"((B)[1]))

#define LDSM_X4(R0, R1, R2, R3, ADDR) \
    asm volatile("ldmatrix.sync.aligned.m8n8.x4.shared.b16 {%0,%1,%2,%3}, [%4];" \
        : "=r"(R0), "=r"(R1), "=r"(R2), "=r"(R3) : "r"(ADDR))

__global__ void __launch_bounds__(256, 2)
k_gemm_mma(int K, const float* __restrict__ bias, int layer) {
    extern __shared__ __align__(16) char smem[];
    uint32_t sbase = (uint32_t)__cvta_generic_to_shared(smem);

    int tid = threadIdx.x;
    int wid = tid >> 5, lid = tid & 31;
    int m0  = blockIdx.x * 128;
    int n0  = blockIdx.y * 128;
    int wm  = (wid & 1) * 64;
    int wn  = (wid >> 1) * 32;
    int lr  = lid >> 2;
    int lc  = lid & 3;

    int t8   = lid >> 3;          // tile index 0..3
    int lrow = lid & 7;
    uint32_t aOff = (uint32_t)((wm + (t8 & 1) * 8 + lrow) * ARB + (t8 >> 1) * 16);
    uint32_t bOff0 = (uint32_t)((wn + (t8 >> 1) * 8 + lrow) * ARB + (t8 & 1) * 16);
    uint32_t bOff1 = bOff0 + (uint32_t)(16 * ARB);

    float c[4][4][4];
    #pragma unroll
    for (int i = 0; i < 4; i++)
        #pragma unroll
        for (int j = 0; j < 4; j++)
            #pragma unroll
            for (int q = 0; q < 4; q++) c[i][j][q] = 0.f;

    auto load_chunk = [&](int kc, char* base) {
        __half* sA = (__half*)base;
        __half* sB = sA + SA_ELEM;
        #pragma unroll
        for (int j = 0; j < 4; j++) {
            int i = tid * 4 + j;
            int r = i >> 3, kg = i & 7;
            size_t go = (size_t)(m0 + r) * K + kc + kg * 8;
            CP16(sA + r * ASTRIDE + kg * 8, g_ah + go);
            size_t gob = (size_t)(n0 + r) * K + kc + kg * 8;
            CP16(sB + r * ASTRIDE + kg * 8, g_wh + gob);
        }
        asm volatile("cp.async.commit_group;" ::: "memory");
    };

    int nch = K >> 6;
    load_chunk(0, smem);

    for (int kc = 0; kc < nch; kc++) {
        if (kc + 1 < nch) {
            load_chunk((kc + 1) << 6, smem + ((kc + 1) & 1) * BUF_BYTES);
            asm volatile("cp.async.wait_group 1;" ::: "memory");
        } else {
            asm volatile("cp.async.wait_group 0;" ::: "memory");
        }
        __syncthreads();

        uint32_t sAaddr = sbase + (kc & 1) * BUF_BYTES;
        uint32_t sBaddr = sAaddr + SA_ELEM * 2;

        #pragma unroll
        for (int ks = 0; ks < 4; ks++) {
            uint32_t kso = (uint32_t)(ks * 32);
            uint32_t bb[4][2];
            LDSM_X4(bb[0][0], bb[0][1], bb[1][0], bb[1][1], sBaddr + bOff0 + kso);
            LDSM_X4(bb[2][0], bb[2][1], bb[3][0], bb[3][1], sBaddr + bOff1 + kso);
            #pragma unroll
            for (int fm = 0; fm < 4; fm++) {
                uint32_t aa[4];
                LDSM_X4(aa[0], aa[1], aa[2], aa[3],
                        sAaddr + aOff + (uint32_t)(fm * 16 * ARB) + kso);
                #pragma unroll
                for (int fn = 0; fn < 4; fn++)
                    MMA16816(c[fm][fn], aa, bb[fn]);
            }
        }
        __syncthreads();
    }

    // ---- fused epilogue: y = acc + rho*woff + bias; h = tanh.approx(y) ----
    const float* woff = g_woff + layer * RANK;
    float woffv[8], biasv[8];
    #pragma unroll
    for (int fn = 0; fn < 4; fn++) {
        int col = n0 + wn + fn * 8 + lc * 2;
        woffv[fn * 2]     = woff[col];
        woffv[fn * 2 + 1] = woff[col + 1];
        biasv[fn * 2]     = bias[col];
        biasv[fn * 2 + 1] = bias[col + 1];
    }

    float ts[8], tq[8];
    #pragma unroll
    for (int j = 0; j < 8; j++) { ts[j] = 0.f; tq[j] = 0.f; }

    #pragma unroll
    for (int fm = 0; fm < 4; fm++) {
        int r0 = m0 + wm + fm * 16 + lr;
        int r1 = r0 + 8;
        float rho0 = 0.f, rho1 = 0.f;
        if (r0 < NN) { float d = g_dinv[r0]; rho0 = d * (g_rhop[r0] + d); }
        if (r1 < NN) { float d = g_dinv[r1]; rho1 = d * (g_rhop[r1] + d); }
        #pragma unroll
        for (int fn = 0; fn < 4; fn++) {
            int col = n0 + wn + fn * 8 + lc * 2;
            float w0v = woffv[fn * 2], w1v = woffv[fn * 2 + 1];
            float b0v = biasv[fn * 2], b1v = biasv[fn * 2 + 1];
            if (r0 < NN) {
                float h00 = tanh_fast(c[fm][fn][0] + rho0 * w0v + b0v);
                float h01 = tanh_fast(c[fm][fn][1] + rho0 * w1v + b1v);
                *(__half2*)(g_hf16 + (size_t)r0 * RANK + col) = __floats2half2_rn(h00, h01);
                ts[fn * 2] += h00;     tq[fn * 2]     = fmaf(h00, h00, tq[fn * 2]);
                ts[fn * 2 + 1] += h01; tq[fn * 2 + 1] = fmaf(h01, h01, tq[fn * 2 + 1]);
            }
            if (r1 < NN) {
                float h10 = tanh_fast(c[fm][fn][2] + rho1 * w0v + b0v);
                float h11 = tanh_fast(c[fm][fn][3] + rho1 * w1v + b1v);
                *(__half2*)(g_hf16 + (size_t)r1 * RANK + col) = __floats2half2_rn(h10, h11);
                ts[fn * 2] += h10;     tq[fn * 2]     = fmaf(h10, h10, tq[fn * 2]);
                ts[fn * 2 + 1] += h11; tq[fn * 2 + 1] = fmaf(h11, h11, tq[fn * 2 + 1]);
            }
        }
    }

    #pragma unroll
    for (int off = 4; off < 32; off <<= 1) {
        #pragma unroll
        for (int j = 0; j < 8; j++) {
            ts[j] += __shfl_xor_sync(0xffffffff, ts[j], off);
            tq[j] += __shfl_xor_sync(0xffffffff, tq[j], off);
        }
    }

    float* red = (float*)smem;   // [0:128) sum, [128:256) sq
    __syncthreads();
    if (tid < 128) { red[tid] = 0.f; red[128 + tid] = 0.f; }
    __syncthreads();
    if (lr == 0) {
        #pragma unroll
        for (int fn = 0; fn < 4; fn++) {
            int lcol = wn + fn * 8 + lc * 2;
            atomicAdd(&red[lcol],           ts[fn * 2]);
            atomicAdd(&red[lcol + 1],       ts[fn * 2 + 1]);
            atomicAdd(&red[128 + lcol],     tq[fn * 2]);
            atomicAdd(&red[128 + lcol + 1], tq[fn * 2 + 1]);
        }
    }
    __syncthreads();
    if (tid < 128) {
        atomicAdd(&g_sum[layer * RANK + n0 + tid],   red[tid]);
        atomicAdd(&g_sumsq[layer * RANK + n0 + tid], red[128 + tid]);
    }
}

// ---------------- launch ----------------------------------------------------
extern "C" void kernel_launch(void* const* d_in, const int* in_sizes, int n_in,
                              void* d_out, int out_size) {
    const float* x     = (const float*)d_in[0];
    const int*   ei    = (const int*)  d_in[1];   // [2, E] int32
    const int*   batch = (const int*)  d_in[2];
    const float* W[3]     = { (const float*)d_in[3],  (const float*)d_in[7],  (const float*)d_in[11] };
    const float* b[3]     = { (const float*)d_in[4],  (const float*)d_in[8],  (const float*)d_in[12] };
    const float* gamma[3] = { (const float*)d_in[5],  (const float*)d_in[9],  (const float*)d_in[13] };
    const float* beta[3]  = { (const float*)d_in[6],  (const float*)d_in[10], (const float*)d_in[14] };
    const int* src = ei;
    const int* dst = ei + EE;
    float* out = (float*)d_out;

    cudaFuncSetAttribute(k_gemm_mma, cudaFuncAttributeMaxDynamicSharedMemorySize, GEMM_SMEM);

    k_init     <<<(NN + 255) / 256, 256>>>();
    k_histconv <<<HISTB + CONVW0B + CONVXB, 256>>>(dst, W[0], x);
    k_dinvscan1<<<98, 256>>>();
    k_scan3gptr<<<98, 256>>>(batch);
    k_scatter  <<<(EE + 255) / 256, 256>>>(src, dst);

    dim3 gemm_grid((NN + 127) / 128, 2);   // 782 x 2
    int ablocks = (NN + ANPB - 1) / ANPB;  // 6250
    int nconv   = RANK * RANK / 256 + 32;  // 288 convW + offset blocks

    // layer 0: agg(x) -> gemm
    k_aggpool<<<ablocks, 256>>>(DIN, ablocks, 0, 0, gamma[0], beta[0], out, W[1]);
    k_gemm_mma<<<gemm_grid, 256, GEMM_SMEM>>>(DIN, b[0], 0);

    // layer boundary 0->1: agg(h0) + pool0 + convW1 + woff1
    k_aggpool<<<ablocks + GG + nconv, 256>>>(RANK, ablocks, GG, 0,
                                             gamma[0], beta[0], out, W[1]);
    k_gemm_mma<<<gemm_grid, 256, GEMM_SMEM>>>(RANK, b[1], 1);

    // layer boundary 1->2
    k_aggpool<<<ablocks + GG + nconv, 256>>>(RANK, ablocks, GG, 1,
                                             gamma[1], beta[1],
                                             out + (size_t)GG * RANK, W[2]);
    k_gemm_mma<<<gemm_grid, 256, GEMM_SMEM>>>(RANK, b[2], 2);

    // final pool (layer 2)
    k_aggpool<<<GG, 256>>>(RANK, 0, GG, 2, gamma[2], beta[2],
                           out + (size_t)2 * GG * RANK, W[2]);
}

// round 16
// speedup vs baseline: 1.0655x; 1.0016x over previous
#include <cuda_runtime.h>
#include <cuda_fp16.h>
#include <math.h>
#include <stdint.h>

#define NN   100000
#define NPAD 100096          // 782 * 128
#define EE   400000
#define GG   2048
#define DIN  128
#define RANK 256

// ---------------- scratch (device globals: zero at module load) -------------
// Invariant: every kernel_launch call leaves these in the all-zero state it
// found them in (self-restoring), except arrays fully overwritten each call.
__device__ __half g_hf16[NPAD * RANK];   // h (tanh out) fp16; also x fp16 (lda=K)
__device__ __half g_ah [NPAD * RANK];    // Agg(h) fp16 (lda = K)
__device__ __half g_wh [RANK * RANK];    // (scale-folded) W^T fp16  [n][k]
__device__ float g_woff[3 * RANK];       // rank-1 BN offset per layer (zeroed at end)
__device__ float g_rhop[NN];             // (zeroed at end)
__device__ int   g_cnt   [NN];           // (zeroed at end)
__device__ int   g_cursor[NN];           // (zeroed at end)
__device__ int   g_rowptr[NN + 1];
__device__ float g_dinv  [NN];
__device__ int   g_esrc[EE];
__device__ float g_ew  [EE];
__device__ int   g_gptr[GG + 1];
__device__ float g_sum  [3 * RANK];      // layers 0,1 zeroed at end; layer 2 at start
__device__ float g_sumsq[3 * RANK];
__device__ int   g_part[128];
__device__ int   g_sync;                 // grid-sync counter (zeroed at end)

__device__ __forceinline__ float tanh_fast(float x) {
    float y;
    asm("tanh.approx.f32 %0, %1;" : "=f"(y) : "f"(x));
    return y;
}

// ---------------- BN param helper -------------------------------------------
__device__ __forceinline__ void bn_params(int layer, int c,
                                          const float* gamma, const float* beta,
                                          float& sc, float& sh) {
    float mu  = g_sum[layer * RANK + c]   * (1.0f / NN);
    float var = g_sumsq[layer * RANK + c] * (1.0f / NN) - mu * mu;
    sc = gamma[c] * rsqrtf(var + 1e-5f);
    sh = beta[c] - mu * sc;
}

// ---------------- hist + convW0 + x->fp16 + zero layer-2 stats ---------------
#define HISTB 1563            // ceil(EE/256)
#define CONVW0B (RANK * DIN / 256)   // 128
#define CONVXB (NN * DIN / 4 / 256)  // 12500
__global__ void k_histconv(const int* __restrict__ dst,
                           const float* __restrict__ W0,
                           const float* __restrict__ x) {
    int b = blockIdx.x;
    if (b < HISTB) {
        int e = b * 256 + threadIdx.x;
        if (e < EE) atomicAdd(&g_cnt[dst[e]], 1);
    } else if (b < HISTB + CONVW0B) {
        int i = (b - HISTB) * 256 + threadIdx.x;     // over RANK*DIN
        int n = i / DIN, k = i - n * DIN;
        g_wh[i] = __float2half_rn(W0[(size_t)k * RANK + n]);
    } else if (b < HISTB + CONVW0B + CONVXB) {
        int i4 = (b - HISTB - CONVW0B) * 256 + threadIdx.x;
        if (i4 < NN * DIN / 4) {
            float4 v = ((const float4*)x)[i4];
            __half2 a = __floats2half2_rn(v.x, v.y);
            __half2 c = __floats2half2_rn(v.z, v.w);
            *(uint2*)(g_hf16 + (size_t)i4 * 4) = make_uint2(*(uint32_t*)&a, *(uint32_t*)&c);
        }
    } else {
        // zero layer-2 BN stats (written later by gemm-2, read by final pool)
        int i = 2 * RANK + threadIdx.x;
        g_sum[i] = 0.f; g_sumsq[i] = 0.f;
    }
}

// fused: dinv + scan phase1 | grid sync | scan phase2+3 + gptr
__global__ void k_scans(const int* __restrict__ batch) {
    __shared__ int sm[256];
    __shared__ int sp[128];
    int b = blockIdx.x, t = threadIdx.x;
    if (b == 0 && t == 0) g_rowptr[NN] = EE;

    int base = b * 1024 + t * 4;
    int v[4]; int s = 0;
    #pragma unroll
    for (int j = 0; j < 4; j++) {
        int i = base + j;
        if (i < NN) {
            int c = g_cnt[i];
            v[j] = c;
            s += c;
            g_dinv[i] = rsqrtf((float)(c + 1));
        } else v[j] = 0;
    }
    sm[t] = s; __syncthreads();
    // block reduction into g_part[b] (keep sm intact: use sp scratch)
    {
        int red = s;
        if (t < 128) sp[t] = 0;
        __syncthreads();
        // simple tree over a copy
        __shared__ int tot[256];
        tot[t] = s; __syncthreads();
        for (int off = 128; off > 0; off >>= 1) {
            if (t < off) tot[t] += tot[t + off];
            __syncthreads();
        }
        if (t == 0) g_part[b] = tot[0];
        (void)red;
    }

    // ---- grid-wide sync (98 blocks, co-resident on 148 SMs) ----
    __threadfence();
    if (t == 0) {
        atomicAdd(&g_sync, 1);
        while (atomicAdd(&g_sync, 0) < 98) { }
    }
    __syncthreads();
    __threadfence();

    // in-block exclusive scan of the 98 block partials
    if (t < 128) sp[t] = (t < 98) ? g_part[t] : 0;
    __syncthreads();
    for (int off = 1; off < 128; off <<= 1) {
        int u = (t >= off && t < 128) ? sp[t - off] : 0;
        __syncthreads();
        if (t < 128) sp[t] += u;
        __syncthreads();
    }
    int blockPrefix = (b > 0) ? sp[b - 1] : 0;   // exclusive

    // intra-block inclusive scan of per-thread sums
    __syncthreads();
    for (int off = 1; off < 256; off <<= 1) {
        int u = (t >= off) ? sm[t - off] : 0;
        __syncthreads();
        sm[t] += u;
        __syncthreads();
    }
    int off0 = blockPrefix + (sm[t] - s);
    int run = 0;
    #pragma unroll
    for (int j = 0; j < 4; j++) {
        int i = base + j;
        if (i < NN) {
            g_rowptr[i] = off0 + run;
            int bi = batch[i];
            if (i == 0) {
                for (int g = 0; g <= bi; g++) g_gptr[g] = 0;
            } else {
                int bp = batch[i - 1];
                for (int g = bp + 1; g <= bi; g++) g_gptr[g] = i;
            }
            if (i == NN - 1) {
                for (int g = bi + 1; g <= GG; g++) g_gptr[g] = NN;
            }
        }
        run += v[j];
    }
}

__global__ void k_scatter(const int* __restrict__ src, const int* __restrict__ dst) {
    int e = blockIdx.x * blockDim.x + threadIdx.x;
    if (e >= EE) return;
    int s = src[e], d = dst[e];
    int pos = g_rowptr[d] + atomicAdd(&g_cursor[d], 1);
    float ds = g_dinv[s];
    g_esrc[pos] = s;
    g_ew[pos]   = ds * g_dinv[d];
    atomicAdd(&g_rhop[d], ds);
}

// ---------------- fused per-layer-boundary kernel ----------------------------
// blocks [0,nagg): aggregation (K cols) h->g_ah
// blocks [nagg, nagg+npool): global max pool of `layer`
// blocks [nagg+npool, ...): convW+woff (zeroTail==0) OR state re-zero (zeroTail==1)
#define ANPB 16
#define ZEROB ((NN + 255) / 256)   // 391
__global__ void __launch_bounds__(256)
k_aggpool(int K, int nagg, int npool, int layer, int zeroTail,
          const float* __restrict__ gamma, const float* __restrict__ beta,
          float* __restrict__ out, const float* __restrict__ Wnext) {
    int bid = blockIdx.x;
    int tid = threadIdx.x;

    if (bid < nagg) {
        // ---- aggregation (x2 unroll; mean degree ~4) ----
        int ncg  = K >> 3;
        int cg   = (tid & (ncg - 1)) * 8;
        int sub  = tid / ncg;
        int nsub = 256 / ncg;
        int v0   = bid * ANPB;

        for (int n = sub; n < ANPB; n += nsub) {
            int v = v0 + n;
            if (v >= NN) break;
            int beg = g_rowptr[v], end = g_rowptr[v + 1];
            float di = g_dinv[v];
            float w0 = di * di;

            float acc[8];
            {
                uint4 u = *(const uint4*)(g_hf16 + (size_t)v * K + cg);
                const __half2* hp = (const __half2*)&u;
                #pragma unroll
                for (int j = 0; j < 4; j++) {
                    float2 f = __half22float2(hp[j]);
                    acc[2 * j]     = w0 * f.x;
                    acc[2 * j + 1] = w0 * f.y;
                }
            }
            int e = beg;
            for (; e + 2 <= end; e += 2) {
                float w1 = g_ew[e], w2 = g_ew[e + 1];
                int   s1 = g_esrc[e], s2 = g_esrc[e + 1];
                uint4 u1 = *(const uint4*)(g_hf16 + (size_t)s1 * K + cg);
                uint4 u2 = *(const uint4*)(g_hf16 + (size_t)s2 * K + cg);
                const __half2* h1 = (const __half2*)&u1;
                const __half2* h2 = (const __half2*)&u2;
                #pragma unroll
                for (int j = 0; j < 4; j++) {
                    float2 f1 = __half22float2(h1[j]);
                    float2 f2 = __half22float2(h2[j]);
                    acc[2 * j]     = fmaf(w1, f1.x, acc[2 * j]);
                    acc[2 * j + 1] = fmaf(w1, f1.y, acc[2 * j + 1]);
                    acc[2 * j]     = fmaf(w2, f2.x, acc[2 * j]);
                    acc[2 * j + 1] = fmaf(w2, f2.y, acc[2 * j + 1]);
                }
            }
            for (; e < end; e++) {
                float w = g_ew[e];
                int   s = g_esrc[e];
                uint4 u = *(const uint4*)(g_hf16 + (size_t)s * K + cg);
                const __half2* hp = (const __half2*)&u;
                #pragma unroll
                for (int j = 0; j < 4; j++) {
                    float2 f = __half22float2(hp[j]);
                    acc[2 * j]     = fmaf(w, f.x, acc[2 * j]);
                    acc[2 * j + 1] = fmaf(w, f.y, acc[2 * j + 1]);
                }
            }

            __align__(16) __half o[8];
            #pragma unroll
            for (int j = 0; j < 8; j++) o[j] = __float2half_rn(acc[j]);
            *(uint4*)(g_ah + (size_t)v * K + cg) = *(uint4*)o;
        }
    } else if (bid < nagg + npool) {
        // ---- pool (scalar per-column, x2 row unroll) ----
        int g = bid - nagg, c = tid;
        int beg = g_gptr[g], end = g_gptr[g + 1];
        float sc, sh;
        bn_params(layer, c, gamma, beta, sc, sh);
        float m0 = -INFINITY, m1 = -INFINITY;
        int r = beg;
        for (; r + 2 <= end; r += 2) {
            m0 = fmaxf(m0, __half2float(g_hf16[(size_t)r * RANK + c]));
            m1 = fmaxf(m1, __half2float(g_hf16[(size_t)(r + 1) * RANK + c]));
        }
        if (r < end) m0 = fmaxf(m0, __half2float(g_hf16[(size_t)r * RANK + c]));
        float m = fmaxf(m0, m1);
        out[(size_t)g * RANK + c] = (end > beg) ? fmaf(sc, m, sh) : 0.0f;
    } else if (!zeroTail) {
        int convB = RANK * RANK / 256;   // 256 (K_w = RANK for layers 1,2)
        int b2 = bid - nagg - npool;
        if (b2 < convB) {
            // ---- convW for layer+1, scale-folded by stats[layer] ----
            int i = b2 * 256 + tid;
            int n = i / RANK, k = i - n * RANK;
            float sc, sh;
            bn_params(layer, k, gamma, beta, sc, sh);
            g_wh[i] = __float2half_rn(Wnext[(size_t)k * RANK + n] * sc);
        } else {
            // ---- rank-1 offset for layer+1 ----
            int b3 = b2 - convB;         // 0..31
            int n = tid;
            int kpb = RANK / 32;
            int k0 = b3 * kpb;
            float o = 0.f;
            for (int k = k0; k < k0 + kpb; k++) {
                float sc, sh;
                bn_params(layer, k, gamma, beta, sc, sh);
                o = fmaf(sh, Wnext[(size_t)k * RANK + n], o);
            }
            atomicAdd(&g_woff[(layer + 1) * RANK + n], o);
        }
    } else {
        // ---- state re-zero for next call (runs with final pool; pool reads
        //      only g_gptr/g_hf16/stats-layer2, none of which we touch) ----
        int i = (bid - nagg - npool) * 256 + tid;
        if (i < NN) { g_cnt[i] = 0; g_cursor[i] = 0; g_rhop[i] = 0.f; }
        if (i < 2 * RANK) { g_sum[i] = 0.f; g_sumsq[i] = 0.f; }
        if (i < 3 * RANK) g_woff[i] = 0.f;
        if (i == 0) g_sync = 0;
    }
}

// ---------------- mma.sync fp16 GEMM (ldmatrix, 2-stage cp.async) ------------
// CTA 128(M) x 128(N), 256 threads (8 warps 2x4), warp 64x32, K chunk 64.
#define ASTRIDE 72
#define ARB  (ASTRIDE * 2)   // 144 bytes per row
#define SA_ELEM (128 * ASTRIDE)
#define SB_ELEM (128 * ASTRIDE)
#define BUF_BYTES ((SA_ELEM + SB_ELEM) * 2)     // 36864
#define GEMM_SMEM (2 * BUF_BYTES)                // 73728

#define CP16(dst, src) do {                                                \
    uint32_t _d = (uint32_t)__cvta_generic_to_shared(dst);                 \
    asm volatile("cp.async.cg.shared.global [%0], [%1], 16;"               \
                 :: "r"(_d), "l"(src));                                    \
} while (0)

#define MMA16816(C, A, B) \
    asm volatile("mma.sync.aligned.m16n8k16.row.col.f32.f16.f16.f32 " \
        "{%0,%1,%2,%3}, {%4,%5,%6,%7}, {%8,%9}, {%0,%1,%2,%3};" \
        : "+f"((C)[0]), "+f"((C)[1]), "+f"((C)[2]), "+f"((C)[3]) \
        : "r"((A)[0]), "r"((A)[1]), "r"((A)[2]), "r"((A)[3]), \
          "r"((B)[0]), "r"((B)[1]))

#define LDSM_X4(R0, R1, R2, R3, ADDR) \
    asm volatile("ldmatrix.sync.aligned.m8n8.x4.shared.b16 {%0,%1,%2,%3}, [%4];" \
        : "=r"(R0), "=r"(R1), "=r"(R2), "=r"(R3) : "r"(ADDR))

__global__ void __launch_bounds__(256, 2)
k_gemm_mma(int K, const float* __restrict__ bias, int layer) {
    extern __shared__ __align__(16) char smem[];
    uint32_t sbase = (uint32_t)__cvta_generic_to_shared(smem);

    int tid = threadIdx.x;
    int wid = tid >> 5, lid = tid & 31;
    int m0  = blockIdx.x * 128;
    int n0  = blockIdx.y * 128;
    int wm  = (wid & 1) * 64;
    int wn  = (wid >> 1) * 32;
    int lr  = lid >> 2;
    int lc  = lid & 3;

    int t8   = lid >> 3;          // tile index 0..3
    int lrow = lid & 7;
    uint32_t aOff = (uint32_t)((wm + (t8 & 1) * 8 + lrow) * ARB + (t8 >> 1) * 16);
    uint32_t bOff0 = (uint32_t)((wn + (t8 >> 1) * 8 + lrow) * ARB + (t8 & 1) * 16);
    uint32_t bOff1 = bOff0 + (uint32_t)(16 * ARB);

    float c[4][4][4];
    #pragma unroll
    for (int i = 0; i < 4; i++)
        #pragma unroll
        for (int j = 0; j < 4; j++)
            #pragma unroll
            for (int q = 0; q < 4; q++) c[i][j][q] = 0.f;

    auto load_chunk = [&](int kc, char* base) {
        __half* sA = (__half*)base;
        __half* sB = sA + SA_ELEM;
        #pragma unroll
        for (int j = 0; j < 4; j++) {
            int i = tid * 4 + j;
            int r = i >> 3, kg = i & 7;
            size_t go = (size_t)(m0 + r) * K + kc + kg * 8;
            CP16(sA + r * ASTRIDE + kg * 8, g_ah + go);
            size_t gob = (size_t)(n0 + r) * K + kc + kg * 8;
            CP16(sB + r * ASTRIDE + kg * 8, g_wh + gob);
        }
        asm volatile("cp.async.commit_group;" ::: "memory");
    };

    int nch = K >> 6;
    load_chunk(0, smem);

    for (int kc = 0; kc < nch; kc++) {
        if (kc + 1 < nch) {
            load_chunk((kc + 1) << 6, smem + ((kc + 1) & 1) * BUF_BYTES);
            asm volatile("cp.async.wait_group 1;" ::: "memory");
        } else {
            asm volatile("cp.async.wait_group 0;" ::: "memory");
        }
        __syncthreads();

        uint32_t sAaddr = sbase + (kc & 1) * BUF_BYTES;
        uint32_t sBaddr = sAaddr + SA_ELEM * 2;

        #pragma unroll
        for (int ks = 0; ks < 4; ks++) {
            uint32_t kso = (uint32_t)(ks * 32);
            uint32_t bb[4][2];
            LDSM_X4(bb[0][0], bb[0][1], bb[1][0], bb[1][1], sBaddr + bOff0 + kso);
            LDSM_X4(bb[2][0], bb[2][1], bb[3][0], bb[3][1], sBaddr + bOff1 + kso);
            #pragma unroll
            for (int fm = 0; fm < 4; fm++) {
                uint32_t aa[4];
                LDSM_X4(aa[0], aa[1], aa[2], aa[3],
                        sAaddr + aOff + (uint32_t)(fm * 16 * ARB) + kso);
                #pragma unroll
                for (int fn = 0; fn < 4; fn++)
                    MMA16816(c[fm][fn], aa, bb[fn]);
            }
        }
        __syncthreads();
    }

    // ---- fused epilogue: y = acc + rho*woff + bias; h = tanh.approx(y) ----
    const float* woff = g_woff + layer * RANK;
    float woffv[8], biasv[8];
    #pragma unroll
    for (int fn = 0; fn < 4; fn++) {
        int col = n0 + wn + fn * 8 + lc * 2;
        woffv[fn * 2]     = woff[col];
        woffv[fn * 2 + 1] = woff[col + 1];
        biasv[fn * 2]     = bias[col];
        biasv[fn * 2 + 1] = bias[col + 1];
    }

    float ts[8], tq[8];
    #pragma unroll
    for (int j = 0; j < 8; j++) { ts[j] = 0.f; tq[j] = 0.f; }

    #pragma unroll
    for (int fm = 0; fm < 4; fm++) {
        int r0 = m0 + wm + fm * 16 + lr;
        int r1 = r0 + 8;
        float rho0 = 0.f, rho1 = 0.f;
        if (r0 < NN) { float d = g_dinv[r0]; rho0 = d * (g_rhop[r0] + d); }
        if (r1 < NN) { float d = g_dinv[r1]; rho1 = d * (g_rhop[r1] + d); }
        #pragma unroll
        for (int fn = 0; fn < 4; fn++) {
            int col = n0 + wn + fn * 8 + lc * 2;
            float w0v = woffv[fn * 2], w1v = woffv[fn * 2 + 1];
            float b0v = biasv[fn * 2], b1v = biasv[fn * 2 + 1];
            if (r0 < NN) {
                float h00 = tanh_fast(c[fm][fn][0] + rho0 * w0v + b0v);
                float h01 = tanh_fast(c[fm][fn][1] + rho0 * w1v + b1v);
                *(__half2*)(g_hf16 + (size_t)r0 * RANK + col) = __floats2half2_rn(h00, h01);
                ts[fn * 2] += h00;     tq[fn * 2]     = fmaf(h00, h00, tq[fn * 2]);
                ts[fn * 2 + 1] += h01; tq[fn * 2 + 1] = fmaf(h01, h01, tq[fn * 2 + 1]);
            }
            if (r1 < NN) {
                float h10 = tanh_fast(c[fm][fn][2] + rho1 * w0v + b0v);
                float h11 = tanh_fast(c[fm][fn][3] + rho1 * w1v + b1v);
                *(__half2*)(g_hf16 + (size_t)r1 * RANK + col) = __floats2half2_rn(h10, h11);
                ts[fn * 2] += h10;     tq[fn * 2]     = fmaf(h10, h10, tq[fn * 2]);
                ts[fn * 2 + 1] += h11; tq[fn * 2 + 1] = fmaf(h11, h11, tq[fn * 2 + 1]);
            }
        }
    }

    #pragma unroll
    for (int off = 4; off < 32; off <<= 1) {
        #pragma unroll
        for (int j = 0; j < 8; j++) {
            ts[j] += __shfl_xor_sync(0xffffffff, ts[j], off);
            tq[j] += __shfl_xor_sync(0xffffffff, tq[j], off);
        }
    }

    float* red = (float*)smem;   // [0:128) sum, [128:256) sq
    __syncthreads();
    if (tid < 128) { red[tid] = 0.f; red[128 + tid] = 0.f; }
    __syncthreads();
    if (lr == 0) {
        #pragma unroll
        for (int fn = 0; fn < 4; fn++) {
            int lcol = wn + fn * 8 + lc * 2;
            atomicAdd(&red[lcol],           ts[fn * 2]);
            atomicAdd(&red[lcol + 1],       ts[fn * 2 + 1]);
            atomicAdd(&red[128 + lcol],     tq[fn * 2]);
            atomicAdd(&red[128 + lcol + 1], tq[fn * 2 + 1]);
        }
    }
    __syncthreads();
    if (tid < 128) {
        atomicAdd(&g_sum[layer * RANK + n0 + tid],   red[tid]);
        atomicAdd(&g_sumsq[layer * RANK + n0 + tid], red[128 + tid]);
    }
}

// ---------------- launch ----------------------------------------------------
extern "C" void kernel_launch(void* const* d_in, const int* in_sizes, int n_in,
                              void* d_out, int out_size) {
    const float* x     = (const float*)d_in[0];
    const int*   ei    = (const int*)  d_in[1];   // [2, E] int32
    const int*   batch = (const int*)  d_in[2];
    const float* W[3]     = { (const float*)d_in[3],  (const float*)d_in[7],  (const float*)d_in[11] };
    const float* b[3]     = { (const float*)d_in[4],  (const float*)d_in[8],  (const float*)d_in[12] };
    const float* gamma[3] = { (const float*)d_in[5],  (const float*)d_in[9],  (const float*)d_in[13] };
    const float* beta[3]  = { (const float*)d_in[6],  (const float*)d_in[10], (const float*)d_in[14] };
    const int* src = ei;
    const int* dst = ei + EE;
    float* out = (float*)d_out;

    cudaFuncSetAttribute(k_gemm_mma, cudaFuncAttributeMaxDynamicSharedMemorySize, GEMM_SMEM);

    k_histconv<<<HISTB + CONVW0B + CONVXB + 1, 256>>>(dst, W[0], x);
    k_scans   <<<98, 256>>>(batch);
    k_scatter <<<(EE + 255) / 256, 256>>>(src, dst);

    dim3 gemm_grid((NN + 127) / 128, 2);   // 782 x 2
    int ablocks = (NN + ANPB - 1) / ANPB;  // 6250
    int nconv   = RANK * RANK / 256 + 32;  // 288 convW + offset blocks

    // layer 0: agg(x) -> gemm
    k_aggpool<<<ablocks, 256>>>(DIN, ablocks, 0, 0, 0, gamma[0], beta[0], out, W[1]);
    k_gemm_mma<<<gemm_grid, 256, GEMM_SMEM>>>(DIN, b[0], 0);

    // layer boundary 0->1: agg(h0) + pool0 + convW1 + woff1
    k_aggpool<<<ablocks + GG + nconv, 256>>>(RANK, ablocks, GG, 0, 0,
                                             gamma[0], beta[0], out, W[1]);
    k_gemm_mma<<<gemm_grid, 256, GEMM_SMEM>>>(RANK, b[1], 1);

    // layer boundary 1->2
    k_aggpool<<<ablocks + GG + nconv, 256>>>(RANK, ablocks, GG, 1, 0,
                                             gamma[1], beta[1],
                                             out + (size_t)GG * RANK, W[2]);
    k_gemm_mma<<<gemm_grid, 256, GEMM_SMEM>>>(RANK, b[2], 2);

    // final pool (layer 2) + state re-zero for next call
    k_aggpool<<<GG + ZEROB, 256>>>(RANK, 0, GG, 2, 1, gamma[2], beta[2],
                                   out + (size_t)2 * GG * RANK, W[2]);
}